// round 1
// baseline (speedup 1.0000x reference)
#include <cuda_runtime.h>

// Affine_Linear: per-token Gram-Schmidt frame + fused 3-matrix linear map.
// Y[tok,f,i] = sum_e A[f,e]*aT[tok,e,i] + Bm[f,e]*bT[tok,e,i] + C[f,e]*cT[tok,e,i]
// where aT/bT/cT are built from J (frame) and X (coords).

#define TOK_PER_GROUP 16
#define THREADS 256
// smem: 3 weight matrices (transposed, [e][f]) + 3 term planes (float4 per (tok,e))
#define SMEM_BYTES (3*64*64*4 + 3*TOK_PER_GROUP*64*16)

__global__ __launch_bounds__(THREADS, 2)
void affine_linear_kernel(const float* __restrict__ X,
                          const float* __restrict__ J,
                          const float* __restrict__ A,
                          const float* __restrict__ Bm,
                          const float* __restrict__ C,
                          float* __restrict__ Y,
                          int ngroups)
{
    extern __shared__ float smem[];
    float*  sWA = smem;                 // [e*64 + f]
    float*  sWB = smem + 4096;
    float*  sWC = smem + 8192;
    float4* sTA = (float4*)(smem + 12288);          // [tok*64 + e]
    float4* sTB = sTA + TOK_PER_GROUP * 64;
    float4* sTC = sTB + TOK_PER_GROUP * 64;

    const int tid = threadIdx.x;

    // ---- load + transpose weights (once per CTA) ----
#pragma unroll
    for (int k = 0; k < 16; k++) {
        int idx = tid + k * THREADS;     // f*64 + e
        int f = idx >> 6, e = idx & 63;
        sWA[e * 64 + f] = A[idx];
        sWB[e * 64 + f] = Bm[idx];
        sWC[e * 64 + f] = C[idx];
    }
    __syncthreads();

    const int w  = tid >> 5;
    const int l  = tid & 31;
    const int t0 = 2 * w;              // warp handles tokens t0, t0+1
    const int f0 = 2 * l;              // lane handles f0, f0+1

    for (int g = blockIdx.x; g < ngroups; g += gridDim.x) {
        const long long tokBase = (long long)g * TOK_PER_GROUP;

        // ---- stage 1: build a/b/c term planes for 16 tokens x 64 e ----
#pragma unroll
        for (int k = 0; k < (TOK_PER_GROUP * 64) / THREADS; k++) {
            int p   = tid + k * THREADS;
            int tok = p >> 6;
            int e   = p & 63;
            long long gt = tokBase + tok;

            const float* Jp = J + ((gt * 64 + e) * 6);
            float2 jx = *(const float2*)(Jp + 0);
            float2 jy = *(const float2*)(Jp + 2);
            float2 jz = *(const float2*)(Jp + 4);
            float a1x = jx.x, a2x = jx.y;
            float a1y = jy.x, a2y = jy.y;
            float a1z = jz.x, a2z = jz.y;

            const float* Xp = X + ((gt * 64 + e) * 3);
            float x0 = Xp[0], x1 = Xp[1], x2 = Xp[2];

            float s1   = fmaf(a1x, a1x, fmaf(a1y, a1y, a1z * a1z));
            float inv1 = rsqrtf(fmaxf(s1, 1e-24f));
            float b1x = a1x * inv1, b1y = a1y * inv1, b1z = a1z * inv1;

            float d  = fmaf(b1x, a2x, fmaf(b1y, a2y, b1z * a2z));
            float ux = fmaf(-d, b1x, a2x);
            float uy = fmaf(-d, b1y, a2y);
            float uz = fmaf(-d, b1z, a2z);
            float s2   = fmaf(ux, ux, fmaf(uy, uy, uz * uz));
            float inv2 = rsqrtf(fmaxf(s2, 1e-24f));
            float b2x = ux * inv2, b2y = uy * inv2, b2z = uz * inv2;

            float b3x = fmaf(b1y, b2z, -b1z * b2y);
            float b3y = fmaf(b1z, b2x, -b1x * b2z);
            float b3z = fmaf(b1x, b2y, -b1y * b2x);

            float rt0 = fmaf(b1x, x0, fmaf(b1y, x1, b1z * x2));
            float rt1 = fmaf(b2x, x0, fmaf(b2y, x1, b2z * x2));
            float rt2 = fmaf(b3x, x0, fmaf(b3y, x1, b3z * x2));

            int si = tok * 64 + e;
            sTA[si] = make_float4(fmaf(b1x, rt0, b2x * rt1),
                                  fmaf(b1y, rt0, b2y * rt1),
                                  fmaf(b1z, rt0, b2z * rt1), 0.f);
            sTB[si] = make_float4(fmaf(b2x, rt0, -b1x * rt1),
                                  fmaf(b2y, rt0, -b1y * rt1),
                                  fmaf(b2z, rt0, -b1z * rt1), 0.f);
            sTC[si] = make_float4(b3x * rt2, b3y * rt2, b3z * rt2, 0.f);
        }
        __syncthreads();

        // ---- stage 2: Y(64x3) = A@a + Bm@b + C@c for 2 tokens per warp ----
        float acc[2][2][3];
#pragma unroll
        for (int t = 0; t < 2; t++)
#pragma unroll
            for (int ff = 0; ff < 2; ff++)
#pragma unroll
                for (int i = 0; i < 3; i++) acc[t][ff][i] = 0.f;

#pragma unroll 4
        for (int e = 0; e < 64; e++) {
            float2 wv[3];
            wv[0] = *(const float2*)&sWA[e * 64 + f0];
            wv[1] = *(const float2*)&sWB[e * 64 + f0];
            wv[2] = *(const float2*)&sWC[e * 64 + f0];
            float4 tt[2][3];
            tt[0][0] = sTA[t0 * 64 + e];
            tt[0][1] = sTB[t0 * 64 + e];
            tt[0][2] = sTC[t0 * 64 + e];
            tt[1][0] = sTA[(t0 + 1) * 64 + e];
            tt[1][1] = sTB[(t0 + 1) * 64 + e];
            tt[1][2] = sTC[(t0 + 1) * 64 + e];
#pragma unroll
            for (int t = 0; t < 2; t++) {
#pragma unroll
                for (int ff = 0; ff < 2; ff++) {
#pragma unroll
                    for (int m = 0; m < 3; m++) {
                        float wgt = ff ? wv[m].y : wv[m].x;
                        acc[t][ff][0] = fmaf(wgt, tt[t][m].x, acc[t][ff][0]);
                        acc[t][ff][1] = fmaf(wgt, tt[t][m].y, acc[t][ff][1]);
                        acc[t][ff][2] = fmaf(wgt, tt[t][m].z, acc[t][ff][2]);
                    }
                }
            }
        }

        // ---- epilogue: lane writes 6 contiguous floats per token ----
#pragma unroll
        for (int t = 0; t < 2; t++) {
            long long gt = tokBase + t0 + t;
            float* Yp = Y + ((gt * 64 + f0) * 3);
            *(float2*)(Yp + 0) = make_float2(acc[t][0][0], acc[t][0][1]);
            *(float2*)(Yp + 2) = make_float2(acc[t][0][2], acc[t][1][0]);
            *(float2*)(Yp + 4) = make_float2(acc[t][1][1], acc[t][1][2]);
        }
        __syncthreads();
    }
}

extern "C" void kernel_launch(void* const* d_in, const int* in_sizes, int n_in,
                              void* d_out, int out_size)
{
    const float* X  = (const float*)d_in[0];
    const float* J  = (const float*)d_in[1];
    const float* A  = (const float*)d_in[2];
    const float* Bm = (const float*)d_in[3];
    const float* C  = (const float*)d_in[4];
    float* Y = (float*)d_out;

    int ntok    = in_sizes[0] / (64 * 3);   // B*N
    int ngroups = ntok / TOK_PER_GROUP;

    cudaFuncSetAttribute(affine_linear_kernel,
                         cudaFuncAttributeMaxDynamicSharedMemorySize, SMEM_BYTES);

    int blocks = 304;                       // 2 CTAs/SM on 152-SM GB300
    if (blocks > ngroups) blocks = ngroups;
    affine_linear_kernel<<<blocks, THREADS, SMEM_BYTES>>>(X, J, A, Bm, C, Y, ngroups);
}

// round 2
// speedup vs baseline: 1.3515x; 1.3515x over previous
#include <cuda_runtime.h>
#include <cuda_bf16.h>
#include <cstdint>

// Affine_Linear via bf16x3-split tensor-core GEMM.
// Per token: Y[f,i] = sum_{e,m} W_m[f,e] * t_m[e,i]
//   -> GEMM rows (tok*3+i), K = e*3+m (192), N = f (64).
// fp32 values split v = hi(bf16) + lo(bf16); Y = Ah*Bh + Ah*Bl + Al*Bh.

#define TOK 64
#define THREADS 384          // 12 warps
#define AROWS 192            // 64 tok * 3 i
#define APITCH 392           // halves; 784B/row -> 49 chunks == 1 mod 8 (no ldmatrix conflicts)
#define BROWS 384            // 192 hi + 192 lo
#define BPITCH 72            // 144B/row -> 9 chunks == 1 mod 8
#define SMEM_A_BYTES (AROWS*APITCH*2)      // 150528
#define SMEM_B_BYTES (BROWS*BPITCH*2)      // 55296
#define SMEM_TOTAL   (SMEM_A_BYTES + SMEM_B_BYTES)   // 205824
#define OPITCH 66            // fp32 epilogue pitch (even -> float2 aligned)

__device__ __forceinline__ uint32_t smem_u32(const void* p) {
    return (uint32_t)__cvta_generic_to_shared(p);
}

__device__ __forceinline__ void ldsm_x4(uint32_t& r0, uint32_t& r1, uint32_t& r2, uint32_t& r3, uint32_t addr) {
    asm volatile("ldmatrix.sync.aligned.m8n8.x4.shared.b16 {%0,%1,%2,%3}, [%4];"
                 : "=r"(r0), "=r"(r1), "=r"(r2), "=r"(r3) : "r"(addr));
}
__device__ __forceinline__ void ldsm_x4_t(uint32_t& r0, uint32_t& r1, uint32_t& r2, uint32_t& r3, uint32_t addr) {
    asm volatile("ldmatrix.sync.aligned.m8n8.x4.trans.shared.b16 {%0,%1,%2,%3}, [%4];"
                 : "=r"(r0), "=r"(r1), "=r"(r2), "=r"(r3) : "r"(addr));
}
__device__ __forceinline__ void mma16816(float* c, uint32_t a0, uint32_t a1, uint32_t a2, uint32_t a3,
                                         uint32_t b0, uint32_t b1) {
    asm volatile("mma.sync.aligned.m16n8k16.row.col.f32.bf16.bf16.f32 "
                 "{%0,%1,%2,%3}, {%4,%5,%6,%7}, {%8,%9}, {%0,%1,%2,%3};"
                 : "+f"(c[0]), "+f"(c[1]), "+f"(c[2]), "+f"(c[3])
                 : "r"(a0), "r"(a1), "r"(a2), "r"(a3), "r"(b0), "r"(b1));
}

__device__ __forceinline__ void split_store(__nv_bfloat16* hi_p, __nv_bfloat16* lo_p, float v) {
    __nv_bfloat16 h = __float2bfloat16(v);
    *hi_p = h;
    *lo_p = __float2bfloat16(v - __bfloat162float(h));
}

__global__ __launch_bounds__(THREADS, 1)
void affine_linear_mma(const float* __restrict__ X,
                       const float* __restrict__ J,
                       const float* __restrict__ A,
                       const float* __restrict__ Bm,
                       const float* __restrict__ C,
                       float* __restrict__ Y)
{
    extern __shared__ char smem[];
    __nv_bfloat16* sA = (__nv_bfloat16*)smem;                    // [row(192)][k(384)] pitch APITCH
    __nv_bfloat16* sB = (__nv_bfloat16*)(smem + SMEM_A_BYTES);   // [k(384)][f(64)] pitch BPITCH
    float* sOut = (float*)smem;                                  // reused after mma

    const int tid = threadIdx.x;
    const long long tokBase = (long long)blockIdx.x * TOK;

    // ---- weights -> sB : rows k=e*3+m (hi), 192+k (lo) ----
    for (int q = tid; q < 4096; q += THREADS) {
        int e = q & 63;                 // q = f*64 + e (coalesced gmem reads)
        int f = q >> 6;
        float w0 = A[q], w1 = Bm[q], w2 = C[q];
        int k = e * 3;
        split_store(&sB[(k+0)*BPITCH + f], &sB[(192+k+0)*BPITCH + f], w0);
        split_store(&sB[(k+1)*BPITCH + f], &sB[(192+k+1)*BPITCH + f], w1);
        split_store(&sB[(k+2)*BPITCH + f], &sB[(192+k+2)*BPITCH + f], w2);
    }

    // ---- stage 1: per-(tok,e) frame build, write split terms into sA ----
    for (int p = tid; p < TOK * 64; p += THREADS) {
        int tok = p >> 6;
        int e   = p & 63;
        long long gt = tokBase + tok;

        const float* Jp = J + (gt * 64 + e) * 6;
        float2 jx = *(const float2*)(Jp + 0);
        float2 jy = *(const float2*)(Jp + 2);
        float2 jz = *(const float2*)(Jp + 4);
        float a1x = jx.x, a2x = jx.y;
        float a1y = jy.x, a2y = jy.y;
        float a1z = jz.x, a2z = jz.y;

        const float* Xp = X + (gt * 64 + e) * 3;
        float x0 = Xp[0], x1 = Xp[1], x2 = Xp[2];

        float s1   = fmaf(a1x, a1x, fmaf(a1y, a1y, a1z * a1z));
        float inv1 = rsqrtf(fmaxf(s1, 1e-24f));
        float b1x = a1x * inv1, b1y = a1y * inv1, b1z = a1z * inv1;

        float d  = fmaf(b1x, a2x, fmaf(b1y, a2y, b1z * a2z));
        float ux = fmaf(-d, b1x, a2x);
        float uy = fmaf(-d, b1y, a2y);
        float uz = fmaf(-d, b1z, a2z);
        float s2   = fmaf(ux, ux, fmaf(uy, uy, uz * uz));
        float inv2 = rsqrtf(fmaxf(s2, 1e-24f));
        float b2x = ux * inv2, b2y = uy * inv2, b2z = uz * inv2;

        float b3x = fmaf(b1y, b2z, -b1z * b2y);
        float b3y = fmaf(b1z, b2x, -b1x * b2z);
        float b3z = fmaf(b1x, b2y, -b1y * b2x);

        float rt0 = fmaf(b1x, x0, fmaf(b1y, x1, b1z * x2));
        float rt1 = fmaf(b2x, x0, fmaf(b2y, x1, b2z * x2));
        float rt2 = fmaf(b3x, x0, fmaf(b3y, x1, b3z * x2));

        // t[m][i]: m=0 a_term, m=1 b_term, m=2 c_term
        float t[3][3];
        t[0][0] = fmaf(b1x, rt0,  b2x * rt1);
        t[0][1] = fmaf(b1y, rt0,  b2y * rt1);
        t[0][2] = fmaf(b1z, rt0,  b2z * rt1);
        t[1][0] = fmaf(b2x, rt0, -b1x * rt1);
        t[1][1] = fmaf(b2y, rt0, -b1y * rt1);
        t[1][2] = fmaf(b2z, rt0, -b1z * rt1);
        t[2][0] = b3x * rt2;
        t[2][1] = b3y * rt2;
        t[2][2] = b3z * rt2;

        int k0 = e * 3;
#pragma unroll
        for (int i = 0; i < 3; i++) {
            __nv_bfloat16* ra = sA + (tok * 3 + i) * APITCH;
#pragma unroll
            for (int m = 0; m < 3; m++)
                split_store(&ra[k0 + m], &ra[192 + k0 + m], t[m][i]);
        }
    }
    __syncthreads();

    // ---- MMA: each warp owns m32 x n32, 3 split passes x 12 k-steps ----
    const int w    = tid >> 5;
    const int lane = tid & 31;
    const int row0 = (w >> 1) * 32;     // 6 M-tiles of 32
    const int n0   = (w & 1) * 32;      // 2 N-tiles of 32

    float acc[2][4][4];
#pragma unroll
    for (int mt = 0; mt < 2; mt++)
#pragma unroll
        for (int nt = 0; nt < 4; nt++)
#pragma unroll
            for (int r = 0; r < 4; r++) acc[mt][nt][r] = 0.f;

    // ldmatrix base addresses (lane-dependent part fixed)
    uint32_t aBase = smem_u32(sA + (row0 + (lane & 15)) * APITCH + ((lane >> 4) << 3));
    uint32_t bBase = smem_u32(sB + (lane & 15) * BPITCH + n0 + ((lane >> 4) << 3));

    const int offA[3] = {0, 0, 192};
    const int offB[3] = {0, 192, 0};

#pragma unroll 1
    for (int pass = 0; pass < 3; pass++) {
#pragma unroll 1
        for (int ks = 0; ks < 12; ks++) {
            int kA = offA[pass] + ks * 16;
            int kB = offB[pass] + ks * 16;

            uint32_t a0[4], a1[4];
            ldsm_x4(a0[0], a0[1], a0[2], a0[3], aBase + (uint32_t)(kA * 2));
            ldsm_x4(a1[0], a1[1], a1[2], a1[3], aBase + (uint32_t)(16 * APITCH * 2 + kA * 2));

            uint32_t b0[4], b1[4];
            ldsm_x4_t(b0[0], b0[1], b0[2], b0[3], bBase + (uint32_t)(kB * BPITCH * 2));
            ldsm_x4_t(b1[0], b1[1], b1[2], b1[3], bBase + (uint32_t)(kB * BPITCH * 2 + 16 * 2));

            mma16816(acc[0][0], a0[0], a0[1], a0[2], a0[3], b0[0], b0[1]);
            mma16816(acc[0][1], a0[0], a0[1], a0[2], a0[3], b0[2], b0[3]);
            mma16816(acc[0][2], a0[0], a0[1], a0[2], a0[3], b1[0], b1[1]);
            mma16816(acc[0][3], a0[0], a0[1], a0[2], a0[3], b1[2], b1[3]);
            mma16816(acc[1][0], a1[0], a1[1], a1[2], a1[3], b0[0], b0[1]);
            mma16816(acc[1][1], a1[0], a1[1], a1[2], a1[3], b0[2], b0[3]);
            mma16816(acc[1][2], a1[0], a1[1], a1[2], a1[3], b1[0], b1[1]);
            mma16816(acc[1][3], a1[0], a1[1], a1[2], a1[3], b1[2], b1[3]);
        }
    }
    __syncthreads();   // all warps done reading sA before reuse

    // ---- accumulators -> sOut (fp32, pitch 66) ----
    {
        int g  = lane >> 2;
        int tq = lane & 3;
#pragma unroll
        for (int mt = 0; mt < 2; mt++) {
            int r0r = row0 + mt * 16 + g;
#pragma unroll
            for (int nt = 0; nt < 4; nt++) {
                int col = n0 + nt * 8 + tq * 2;
                *(float2*)&sOut[r0r * OPITCH + col]       = make_float2(acc[mt][nt][0], acc[mt][nt][1]);
                *(float2*)&sOut[(r0r + 8) * OPITCH + col] = make_float2(acc[mt][nt][2], acc[mt][nt][3]);
            }
        }
    }
    __syncthreads();

    // ---- sOut -> Y (coalesced gmem) ----
    float* Yp = Y + tokBase * 192;
    for (int idx = tid; idx < TOK * 192; idx += THREADS) {
        int tok = idx / 192;
        int rem = idx - tok * 192;
        int f = rem / 3;
        int i = rem - f * 3;
        Yp[idx] = sOut[(tok * 3 + i) * OPITCH + f];
    }
}

extern "C" void kernel_launch(void* const* d_in, const int* in_sizes, int n_in,
                              void* d_out, int out_size)
{
    const float* X  = (const float*)d_in[0];
    const float* J  = (const float*)d_in[1];
    const float* A  = (const float*)d_in[2];
    const float* Bm = (const float*)d_in[3];
    const float* C  = (const float*)d_in[4];
    float* Y = (float*)d_out;

    int ntok = in_sizes[0] / (64 * 3);   // B*N = 65536
    int blocks = ntok / TOK;             // 1024

    cudaFuncSetAttribute(affine_linear_mma,
                         cudaFuncAttributeMaxDynamicSharedMemorySize, SMEM_TOTAL);
    affine_linear_mma<<<blocks, THREADS, SMEM_TOTAL>>>(X, J, A, Bm, C, Y);
}

// round 3
// speedup vs baseline: 2.0360x; 1.5064x over previous
#include <cuda_runtime.h>
#include <cuda_bf16.h>
#include <cstdint>

// Warp-specialized Affine_Linear:
//   9 producer warps: frame build (Gram-Schmidt) -> split-bf16 terms into double-buffered sA
//   3 consumer warps: m32n64 HMMA tiles, fused bf16x3-split passes, epilogue to Y
// Y[(tok,i), f] = sum_k T[(tok,i),k] * W[k,f],  k = e*3+m, K=192, split hi/lo.

#define THREADS 384
#define NPROD   288            // 9 producer warps
#define TOKBUF  32             // tokens per buffer
#define ROWSB   96             // TOKBUF*3 GEMM rows
#define APITCH  392            // halves/row (784B, 49 chunks == 1 mod 8 -> ldsm conflict-free)
#define BPITCH  72             // halves/row for B (144B, 9 chunks == 1 mod 8)
#define OPITCH  66             // fp32 epilogue pitch
#define SB_BYTES   (384*BPITCH*2)          // 55296
#define ABUF_BYTES (ROWSB*APITCH*2)        // 75264
#define SMEM_TOTAL (SB_BYTES + 2*ABUF_BYTES) // 205824

__device__ __forceinline__ uint32_t smem_u32(const void* p) {
    return (uint32_t)__cvta_generic_to_shared(p);
}
__device__ __forceinline__ void ldsm_x4(uint32_t* r, uint32_t addr) {
    asm volatile("ldmatrix.sync.aligned.m8n8.x4.shared.b16 {%0,%1,%2,%3}, [%4];"
                 : "=r"(r[0]), "=r"(r[1]), "=r"(r[2]), "=r"(r[3]) : "r"(addr));
}
__device__ __forceinline__ void ldsm_x4_t(uint32_t* r, uint32_t addr) {
    asm volatile("ldmatrix.sync.aligned.m8n8.x4.trans.shared.b16 {%0,%1,%2,%3}, [%4];"
                 : "=r"(r[0]), "=r"(r[1]), "=r"(r[2]), "=r"(r[3]) : "r"(addr));
}
__device__ __forceinline__ void mma16816(float* c, const uint32_t* a, uint32_t b0, uint32_t b1) {
    asm volatile("mma.sync.aligned.m16n8k16.row.col.f32.bf16.bf16.f32 "
                 "{%0,%1,%2,%3}, {%4,%5,%6,%7}, {%8,%9}, {%0,%1,%2,%3};"
                 : "+f"(c[0]), "+f"(c[1]), "+f"(c[2]), "+f"(c[3])
                 : "r"(a[0]), "r"(a[1]), "r"(a[2]), "r"(a[3]), "r"(b0), "r"(b1));
}

// split v = hi(bf16) + lo(bf16); store packed pairs (v0,v1) at hi ptr, lo ptr.
__device__ __forceinline__ void split2p(__nv_bfloat16* hi, __nv_bfloat16* lo, float v0, float v1) {
    __nv_bfloat16 h0 = __float2bfloat16(v0);
    __nv_bfloat16 h1 = __float2bfloat16(v1);
    *(__nv_bfloat162*)hi = __halves2bfloat162(h0, h1);
    *(__nv_bfloat162*)lo = __halves2bfloat162(__float2bfloat16(v0 - __bfloat162float(h0)),
                                              __float2bfloat16(v1 - __bfloat162float(h1)));
}

__device__ __forceinline__ void frame_terms(float a1x, float a2x, float a1y, float a2y,
                                            float a1z, float a2z,
                                            float x0, float x1, float x2, float t[3][3]) {
    float s1   = fmaf(a1x, a1x, fmaf(a1y, a1y, a1z * a1z));
    float inv1 = rsqrtf(fmaxf(s1, 1e-24f));
    float b1x = a1x * inv1, b1y = a1y * inv1, b1z = a1z * inv1;

    float d  = fmaf(b1x, a2x, fmaf(b1y, a2y, b1z * a2z));
    float ux = fmaf(-d, b1x, a2x);
    float uy = fmaf(-d, b1y, a2y);
    float uz = fmaf(-d, b1z, a2z);
    float s2   = fmaf(ux, ux, fmaf(uy, uy, uz * uz));
    float inv2 = rsqrtf(fmaxf(s2, 1e-24f));
    float b2x = ux * inv2, b2y = uy * inv2, b2z = uz * inv2;

    float b3x = fmaf(b1y, b2z, -b1z * b2y);
    float b3y = fmaf(b1z, b2x, -b1x * b2z);
    float b3z = fmaf(b1x, b2y, -b1y * b2x);

    float rt0 = fmaf(b1x, x0, fmaf(b1y, x1, b1z * x2));
    float rt1 = fmaf(b2x, x0, fmaf(b2y, x1, b2z * x2));
    float rt2 = fmaf(b3x, x0, fmaf(b3y, x1, b3z * x2));

    t[0][0] = fmaf(b1x, rt0,  b2x * rt1);
    t[0][1] = fmaf(b1y, rt0,  b2y * rt1);
    t[0][2] = fmaf(b1z, rt0,  b2z * rt1);
    t[1][0] = fmaf(b2x, rt0, -b1x * rt1);
    t[1][1] = fmaf(b2y, rt0, -b1y * rt1);
    t[1][2] = fmaf(b2z, rt0, -b1z * rt1);
    t[2][0] = b3x * rt2;
    t[2][1] = b3y * rt2;
    t[2][2] = b3z * rt2;
}

__global__ __launch_bounds__(THREADS, 1)
void affine_ws(const float* __restrict__ X,
               const float* __restrict__ J,
               const float* __restrict__ A,
               const float* __restrict__ Bm,
               const float* __restrict__ C,
               float* __restrict__ Y,
               int ngroups)
{
    extern __shared__ char smem[];
    __nv_bfloat16* sB  = (__nv_bfloat16*)smem;                  // [k(384)][f(64)] pitch BPITCH
    __nv_bfloat16* sA0 = (__nv_bfloat16*)(smem + SB_BYTES);     // two buffers of [96][384+pad]

    const int tid = threadIdx.x;

    // ---- weights -> sB, split hi/lo, packed bf16x2 along f (once per CTA) ----
    for (int q = tid; q < 2048; q += THREADS) {
        int e  = q & 63;
        int f0 = (q >> 6) << 1;
        float wa0 = A[f0 * 64 + e],  wa1 = A[(f0 + 1) * 64 + e];
        float wb0 = Bm[f0 * 64 + e], wb1 = Bm[(f0 + 1) * 64 + e];
        float wc0 = C[f0 * 64 + e],  wc1 = C[(f0 + 1) * 64 + e];
        int k = e * 3;
        split2p(&sB[(k+0)*BPITCH + f0], &sB[(192+k+0)*BPITCH + f0], wa0, wa1);
        split2p(&sB[(k+1)*BPITCH + f0], &sB[(192+k+1)*BPITCH + f0], wb0, wb1);
        split2p(&sB[(k+2)*BPITCH + f0], &sB[(192+k+2)*BPITCH + f0], wc0, wc1);
    }
    __syncthreads();

    if (tid < NPROD) {
        // ================= PRODUCERS (warps 0-8) =================
        int it = 0;
        for (int g = blockIdx.x; g < ngroups; g += gridDim.x, it++) {
            int buf = it & 1;
            if (it >= 2) {
                int bid = 3 + buf;   // EMPTY barrier
                asm volatile("bar.sync %0, %1;" :: "r"(bid), "n"(THREADS) : "memory");
            }
            __nv_bfloat16* sA = sA0 + buf * (ABUF_BYTES / 2);
            long long tokBase = (long long)g * TOKBUF;

            for (int p = tid; p < TOKBUF * 32; p += NPROD) {
                int tok = p >> 5;
                int e0  = (p & 31) << 1;
                long long base = (tokBase + tok) * 64 + e0;

                const float4* Jp = (const float4*)(J + base * 6);  // 12 floats (2 points)
                float4 j0 = Jp[0], j1 = Jp[1], j2 = Jp[2];
                const float2* Xp = (const float2*)(X + base * 3);  // 6 floats
                float2 xa = Xp[0], xb = Xp[1], xc = Xp[2];

                float t0[3][3], t1[3][3];
                frame_terms(j0.x, j0.y, j0.z, j0.w, j1.x, j1.y, xa.x, xa.y, xb.x, t0);
                frame_terms(j1.z, j1.w, j2.x, j2.y, j2.z, j2.w, xb.y, xc.x, xc.y, t1);

                int k0 = 3 * e0;                 // halves; 6*e0 bytes -> 4B aligned
#pragma unroll
                for (int i = 0; i < 3; i++) {
                    __nv_bfloat16* r = sA + (tok * 3 + i) * APITCH + k0;
                    split2p(r + 0, r + 192 + 0, t0[0][i], t0[1][i]);
                    split2p(r + 2, r + 192 + 2, t0[2][i], t1[0][i]);
                    split2p(r + 4, r + 192 + 4, t1[1][i], t1[2][i]);
                }
            }
            {
                int bid = 1 + buf;   // FULL barrier
                asm volatile("bar.arrive %0, %1;" :: "r"(bid), "n"(THREADS) : "memory");
            }
        }
    } else {
        // ================= CONSUMERS (warps 9-11) =================
        const int ctid = tid - NPROD;       // 0..95
        const int cw   = ctid >> 5;         // tile 0..2 (m32 each)
        const int lane = tid & 31;

        const uint32_t bBase = smem_u32(sB + (lane & 15) * BPITCH + ((lane >> 4) << 3));

        int it = 0;
        for (int g = blockIdx.x; g < ngroups; g += gridDim.x, it++) {
            int buf = it & 1;
            {
                int bid = 1 + buf;   // FULL
                asm volatile("bar.sync %0, %1;" :: "r"(bid), "n"(THREADS) : "memory");
            }
            __nv_bfloat16* sA = sA0 + buf * (ABUF_BYTES / 2);
            float* sOut = (float*)sA;

            uint32_t aBase = smem_u32(sA + (cw * 32 + (lane & 15)) * APITCH + ((lane >> 4) << 3));

            float acc[2][8][4];
#pragma unroll
            for (int mt = 0; mt < 2; mt++)
#pragma unroll
                for (int q = 0; q < 8; q++)
#pragma unroll
                    for (int r = 0; r < 4; r++) acc[mt][q][r] = 0.f;

#pragma unroll 2
            for (int ks = 0; ks < 12; ks++) {
                uint32_t ao = (uint32_t)(ks * 32);       // 16 halves per kstep
                uint32_t ah0[4], ah1[4], al0[4], al1[4];
                ldsm_x4(ah0, aBase + ao);
                ldsm_x4(ah1, aBase + 16 * APITCH * 2 + ao);
                ldsm_x4(al0, aBase + 384 + ao);          // lo plane: +192 halves
                ldsm_x4(al1, aBase + 16 * APITCH * 2 + 384 + ao);

                uint32_t bo = (uint32_t)(ks * 16 * BPITCH * 2);
                uint32_t bh[4][4], bl[4][4];
#pragma unroll
                for (int q = 0; q < 4; q++) {
                    ldsm_x4_t(bh[q], bBase + bo + q * 32);
                    ldsm_x4_t(bl[q], bBase + bo + 192 * BPITCH * 2 + q * 32);
                }
#pragma unroll
                for (int q = 0; q < 4; q++) {
#pragma unroll
                    for (int j = 0; j < 2; j++) {
                        uint32_t p0 = bh[q][2*j], p1 = bh[q][2*j+1];
                        uint32_t l0 = bl[q][2*j], l1 = bl[q][2*j+1];
                        float* c0 = acc[0][2*q+j];
                        float* c1 = acc[1][2*q+j];
                        mma16816(c0, ah0, p0, p1);   // Ah*Bh
                        mma16816(c1, ah1, p0, p1);
                        mma16816(c0, al0, p0, p1);   // Al*Bh
                        mma16816(c1, al1, p0, p1);
                        mma16816(c0, ah0, l0, l1);   // Ah*Bl
                        mma16816(c1, ah1, l0, l1);
                    }
                }
            }

            // all consumer reads of this buffer done before sOut overwrite
            asm volatile("bar.sync 5, 96;" ::: "memory");

            {
                int gq = lane >> 2, tq = lane & 3;
#pragma unroll
                for (int mt = 0; mt < 2; mt++) {
                    int r = cw * 32 + mt * 16 + gq;
#pragma unroll
                    for (int q = 0; q < 8; q++) {
                        int col = q * 8 + tq * 2;
                        *(float2*)&sOut[r * OPITCH + col] =
                            make_float2(acc[mt][q][0], acc[mt][q][1]);
                        *(float2*)&sOut[(r + 8) * OPITCH + col] =
                            make_float2(acc[mt][q][2], acc[mt][q][3]);
                    }
                }
            }
            asm volatile("bar.sync 5, 96;" ::: "memory");

            // coalesced copy sOut -> Y
            {
                long long tokBase = (long long)g * TOKBUF;
                float* Yp = Y + tokBase * 192;
                for (int idx = ctid; idx < TOKBUF * 192; idx += 96) {
                    int tok = idx / 192;
                    int rem = idx - tok * 192;
                    int f  = rem / 3;
                    int i2 = rem - f * 3;
                    Yp[idx] = sOut[(tok * 3 + i2) * OPITCH + f];
                }
            }
            {
                int bid = 3 + buf;   // EMPTY
                asm volatile("bar.arrive %0, %1;" :: "r"(bid), "n"(THREADS) : "memory");
            }
        }
    }
}

extern "C" void kernel_launch(void* const* d_in, const int* in_sizes, int n_in,
                              void* d_out, int out_size)
{
    const float* X  = (const float*)d_in[0];
    const float* J  = (const float*)d_in[1];
    const float* A  = (const float*)d_in[2];
    const float* Bm = (const float*)d_in[3];
    const float* C  = (const float*)d_in[4];
    float* Y = (float*)d_out;

    int ntok    = in_sizes[0] / (64 * 3);   // B*N
    int ngroups = ntok / TOKBUF;            // 2048

    cudaFuncSetAttribute(affine_ws,
                         cudaFuncAttributeMaxDynamicSharedMemorySize, SMEM_TOTAL);

    int blocks = 152;                        // persistent, ~1 CTA/SM on GB300
    if (blocks > ngroups) blocks = ngroups;
    affine_ws<<<blocks, THREADS, SMEM_TOTAL>>>(X, J, A, Bm, C, Y, ngroups);
}

// round 5
// speedup vs baseline: 2.0492x; 1.0065x over previous
#include <cuda_runtime.h>
#include <cuda_bf16.h>
#include <cstdint>

// Warp-specialized Affine_Linear (HMMA path; tcgen05 unavailable on compute_103 PTX target).
//  10 producer warps: frame build -> split-bf16 terms into double-buffered sA,
//                     plus Y epilogue copy of the previous group (overlaps consumer MMA).
//   6 consumer warps: m32n32 HMMA tiles, fused bf16x3-split, acc -> sOut (in consumed buffer).

#define THREADS 512
#define NPROD   320            // 10 producer warps
#define NCONS   192            // 6 consumer warps
#define TOKBUF  32
#define APITCH  392            // halves/row (784B = 49 chunks == 1 mod 8 -> ldsm conflict-free)
#define BPITCH  72             // halves/row (144B = 9 chunks == 1 mod 8)
#define OPITCH  66
#define SB_BYTES   (384*BPITCH*2)            // 55296
#define ABUF_BYTES (96*APITCH*2)             // 75264
#define SMEM_TOTAL (SB_BYTES + 2*ABUF_BYTES) // 205824

__device__ __forceinline__ uint32_t smem_u32(const void* p) {
    return (uint32_t)__cvta_generic_to_shared(p);
}
__device__ __forceinline__ void ldsm_x4(uint32_t* r, uint32_t addr) {
    asm volatile("ldmatrix.sync.aligned.m8n8.x4.shared.b16 {%0,%1,%2,%3}, [%4];"
                 : "=r"(r[0]), "=r"(r[1]), "=r"(r[2]), "=r"(r[3]) : "r"(addr));
}
__device__ __forceinline__ void ldsm_x4_t(uint32_t* r, uint32_t addr) {
    asm volatile("ldmatrix.sync.aligned.m8n8.x4.trans.shared.b16 {%0,%1,%2,%3}, [%4];"
                 : "=r"(r[0]), "=r"(r[1]), "=r"(r[2]), "=r"(r[3]) : "r"(addr));
}
__device__ __forceinline__ void mma16816(float* c, const uint32_t* a, uint32_t b0, uint32_t b1) {
    asm volatile("mma.sync.aligned.m16n8k16.row.col.f32.bf16.bf16.f32 "
                 "{%0,%1,%2,%3}, {%4,%5,%6,%7}, {%8,%9}, {%0,%1,%2,%3};"
                 : "+f"(c[0]), "+f"(c[1]), "+f"(c[2]), "+f"(c[3])
                 : "r"(a[0]), "r"(a[1]), "r"(a[2]), "r"(a[3]), "r"(b0), "r"(b1));
}

__device__ __forceinline__ void split2p(__nv_bfloat16* hi, __nv_bfloat16* lo, float v0, float v1) {
    __nv_bfloat16 h0 = __float2bfloat16(v0);
    __nv_bfloat16 h1 = __float2bfloat16(v1);
    *(__nv_bfloat162*)hi = __halves2bfloat162(h0, h1);
    *(__nv_bfloat162*)lo = __halves2bfloat162(__float2bfloat16(v0 - __bfloat162float(h0)),
                                              __float2bfloat16(v1 - __bfloat162float(h1)));
}

__device__ __forceinline__ void frame_terms(float a1x, float a2x, float a1y, float a2y,
                                            float a1z, float a2z,
                                            float x0, float x1, float x2, float t[3][3]) {
    float s1   = fmaf(a1x, a1x, fmaf(a1y, a1y, a1z * a1z));
    float inv1 = rsqrtf(fmaxf(s1, 1e-24f));
    float b1x = a1x * inv1, b1y = a1y * inv1, b1z = a1z * inv1;

    float d  = fmaf(b1x, a2x, fmaf(b1y, a2y, b1z * a2z));
    float ux = fmaf(-d, b1x, a2x);
    float uy = fmaf(-d, b1y, a2y);
    float uz = fmaf(-d, b1z, a2z);
    float s2   = fmaf(ux, ux, fmaf(uy, uy, uz * uz));
    float inv2 = rsqrtf(fmaxf(s2, 1e-24f));
    float b2x = ux * inv2, b2y = uy * inv2, b2z = uz * inv2;

    float b3x = fmaf(b1y, b2z, -b1z * b2y);
    float b3y = fmaf(b1z, b2x, -b1x * b2z);
    float b3z = fmaf(b1x, b2y, -b1y * b2x);

    float rt0 = fmaf(b1x, x0, fmaf(b1y, x1, b1z * x2));
    float rt1 = fmaf(b2x, x0, fmaf(b2y, x1, b2z * x2));
    float rt2 = fmaf(b3x, x0, fmaf(b3y, x1, b3z * x2));

    t[0][0] = fmaf(b1x, rt0,  b2x * rt1);
    t[0][1] = fmaf(b1y, rt0,  b2y * rt1);
    t[0][2] = fmaf(b1z, rt0,  b2z * rt1);
    t[1][0] = fmaf(b2x, rt0, -b1x * rt1);
    t[1][1] = fmaf(b2y, rt0, -b1y * rt1);
    t[1][2] = fmaf(b2z, rt0, -b1z * rt1);
    t[2][0] = b3x * rt2;
    t[2][1] = b3y * rt2;
    t[2][2] = b3z * rt2;
}

// Producer-side epilogue: gather sOut (rows=(tok*3+i), cols=f) into contiguous Y.
__device__ __forceinline__ void y_copy(const float* __restrict__ sOut,
                                       float* __restrict__ Y, long long g, int tid)
{
    float* Yp = Y + g * (TOKBUF * 192);
    for (int q = tid; q < (TOKBUF * 192) / 4; q += NPROD) {
        int b0 = q * 4;
        float v[4];
#pragma unroll
        for (int u = 0; u < 4; u++) {
            int r2  = b0 + u;
            int tok = r2 / 192;
            int rem = r2 - tok * 192;
            int f   = rem / 3;
            int i2  = rem - f * 3;
            v[u] = sOut[(tok * 3 + i2) * OPITCH + f];
        }
        *(float4*)(Yp + b0) = make_float4(v[0], v[1], v[2], v[3]);
    }
}

__global__ __launch_bounds__(THREADS, 1)
void affine_ws2(const float* __restrict__ X,
                const float* __restrict__ J,
                const float* __restrict__ A,
                const float* __restrict__ Bm,
                const float* __restrict__ C,
                float* __restrict__ Y,
                int ngroups)
{
    extern __shared__ char smem[];
    __nv_bfloat16* sB  = (__nv_bfloat16*)smem;               // [k(384)][f(64)] pitch BPITCH
    __nv_bfloat16* sA0 = (__nv_bfloat16*)(smem + SB_BYTES);  // two buffers [96][APITCH]

    const int tid = threadIdx.x;

    // ---- weights -> sB, split hi/lo, packed bf16x2 along f ----
    for (int q = tid; q < 2048; q += THREADS) {
        int e  = q & 63;
        int f0 = (q >> 6) << 1;
        float wa0 = A[f0 * 64 + e],  wa1 = A[(f0 + 1) * 64 + e];
        float wb0 = Bm[f0 * 64 + e], wb1 = Bm[(f0 + 1) * 64 + e];
        float wc0 = C[f0 * 64 + e],  wc1 = C[(f0 + 1) * 64 + e];
        int k = e * 3;
        split2p(&sB[(k+0)*BPITCH + f0], &sB[(192+k+0)*BPITCH + f0], wa0, wa1);
        split2p(&sB[(k+1)*BPITCH + f0], &sB[(192+k+1)*BPITCH + f0], wb0, wb1);
        split2p(&sB[(k+2)*BPITCH + f0], &sB[(192+k+2)*BPITCH + f0], wc0, wc1);
    }
    __syncthreads();

    // count of groups this CTA processes
    int nit = 0;
    for (int g = blockIdx.x; g < ngroups; g += gridDim.x) nit++;

    if (tid < NPROD) {
        // ================= PRODUCERS (warps 0-9) =================
        int it = 0;
        for (int g = blockIdx.x; g < ngroups; g += gridDim.x, it++) {
            int buf = it & 1;
            __nv_bfloat16* sA = sA0 + buf * (ABUF_BYTES / 2);

            if (it >= 2) {
                int bid = 3 + buf;   // EMPTY: consumers finished sOut for group it-2
                asm volatile("bar.sync %0, %1;" :: "r"(bid), "n"(THREADS) : "memory");
                y_copy((const float*)sA, Y,
                       (long long)blockIdx.x + (long long)(it - 2) * gridDim.x, tid);
                // producers must all finish reading sOut before any overwrite
                asm volatile("bar.sync 6, %0;" :: "n"(NPROD) : "memory");
            }

            long long tokBase = (long long)g * TOKBUF;
            for (int p = tid; p < TOKBUF * 32; p += NPROD) {
                int tok = p >> 5;
                int e0  = (p & 31) << 1;
                long long base = (tokBase + tok) * 64 + e0;

                const float4* Jp = (const float4*)(J + base * 6);
                float4 j0 = Jp[0], j1 = Jp[1], j2 = Jp[2];
                const float2* Xp = (const float2*)(X + base * 3);
                float2 xa = Xp[0], xb = Xp[1], xc = Xp[2];

                float t0[3][3], t1[3][3];
                frame_terms(j0.x, j0.y, j0.z, j0.w, j1.x, j1.y, xa.x, xa.y, xb.x, t0);
                frame_terms(j1.z, j1.w, j2.x, j2.y, j2.z, j2.w, xb.y, xc.x, xc.y, t1);

                int k0 = 3 * e0;
#pragma unroll
                for (int i = 0; i < 3; i++) {
                    __nv_bfloat16* r = sA + (tok * 3 + i) * APITCH + k0;
                    split2p(r + 0, r + 192 + 0, t0[0][i], t0[1][i]);
                    split2p(r + 2, r + 192 + 2, t0[2][i], t1[0][i]);
                    split2p(r + 4, r + 192 + 4, t1[1][i], t1[2][i]);
                }
            }
            {
                int bid = 1 + buf;   // FULL
                asm volatile("bar.arrive %0, %1;" :: "r"(bid), "n"(THREADS) : "memory");
            }
        }
        // ---- drain: copy out the last <=2 sOut buffers ----
#pragma unroll 1
        for (int k = 0; k < 2; k++) {
            int itd = nit + k;
            int src = itd - 2;
            if (src < 0 || src >= nit) continue;
            int buf = itd & 1;
            int bid = 3 + buf;
            asm volatile("bar.sync %0, %1;" :: "r"(bid), "n"(THREADS) : "memory");
            y_copy((const float*)(sA0 + buf * (ABUF_BYTES / 2)), Y,
                   (long long)blockIdx.x + (long long)src * gridDim.x, tid);
        }
    } else {
        // ================= CONSUMERS (warps 10-15) =================
        const int cw   = (tid - NPROD) >> 5;   // 0..5
        const int lane = tid & 31;
        const int row0 = (cw >> 1) * 32;       // 3 m-tiles
        const int n0   = (cw & 1) * 32;        // 2 n-tiles

        const uint32_t bBase = smem_u32(sB + (lane & 15) * BPITCH + n0 + ((lane >> 4) << 3));

        int it = 0;
        for (int g = blockIdx.x; g < ngroups; g += gridDim.x, it++) {
            int buf = it & 1;
            {
                int bid = 1 + buf;   // FULL
                asm volatile("bar.sync %0, %1;" :: "r"(bid), "n"(THREADS) : "memory");
            }
            __nv_bfloat16* sA = sA0 + buf * (ABUF_BYTES / 2);
            float* sOut = (float*)sA;

            uint32_t aBase = smem_u32(sA + (row0 + (lane & 15)) * APITCH + ((lane >> 4) << 3));

            float acc[2][4][4];
#pragma unroll
            for (int mt = 0; mt < 2; mt++)
#pragma unroll
                for (int q = 0; q < 4; q++)
#pragma unroll
                    for (int r = 0; r < 4; r++) acc[mt][q][r] = 0.f;

#pragma unroll 2
            for (int ks = 0; ks < 12; ks++) {
                uint32_t ao = (uint32_t)(ks * 32);
                uint32_t ah0[4], ah1[4], al0[4], al1[4];
                ldsm_x4(ah0, aBase + ao);
                ldsm_x4(ah1, aBase + 16 * APITCH * 2 + ao);
                ldsm_x4(al0, aBase + 384 + ao);
                ldsm_x4(al1, aBase + 16 * APITCH * 2 + 384 + ao);

                uint32_t bo = (uint32_t)(ks * 16 * BPITCH * 2);
                uint32_t bh[2][4], bl[2][4];
#pragma unroll
                for (int q = 0; q < 2; q++) {
                    ldsm_x4_t(bh[q], bBase + bo + q * 32);
                    ldsm_x4_t(bl[q], bBase + bo + 192 * BPITCH * 2 + q * 32);
                }
#pragma unroll
                for (int q = 0; q < 2; q++) {
#pragma unroll
                    for (int j = 0; j < 2; j++) {
                        uint32_t p0 = bh[q][2*j], p1 = bh[q][2*j+1];
                        uint32_t l0 = bl[q][2*j], l1 = bl[q][2*j+1];
                        float* c0 = acc[0][2*q+j];
                        float* c1 = acc[1][2*q+j];
                        mma16816(c0, ah0, p0, p1);   // Ah*Bh
                        mma16816(c1, ah1, p0, p1);
                        mma16816(c0, al0, p0, p1);   // Al*Bh
                        mma16816(c1, al1, p0, p1);
                        mma16816(c0, ah0, l0, l1);   // Ah*Bl
                        mma16816(c1, ah1, l0, l1);
                    }
                }
            }

            // all consumers done reading sA before sOut overwrite
            asm volatile("bar.sync 5, %0;" :: "n"(NCONS) : "memory");

            {
                int gq = lane >> 2, tq = lane & 3;
#pragma unroll
                for (int mt = 0; mt < 2; mt++) {
                    int r = row0 + mt * 16 + gq;
#pragma unroll
                    for (int q = 0; q < 4; q++) {
                        int col = n0 + q * 8 + tq * 2;
                        *(float2*)&sOut[r * OPITCH + col] =
                            make_float2(acc[mt][q][0], acc[mt][q][1]);
                        *(float2*)&sOut[(r + 8) * OPITCH + col] =
                            make_float2(acc[mt][q][2], acc[mt][q][3]);
                    }
                }
            }
            {
                int bid = 3 + buf;   // EMPTY (sOut ready for producer-side Y copy)
                asm volatile("bar.arrive %0, %1;" :: "r"(bid), "n"(THREADS) : "memory");
            }
        }
    }
}

extern "C" void kernel_launch(void* const* d_in, const int* in_sizes, int n_in,
                              void* d_out, int out_size)
{
    const float* X  = (const float*)d_in[0];
    const float* J  = (const float*)d_in[1];
    const float* A  = (const float*)d_in[2];
    const float* Bm = (const float*)d_in[3];
    const float* C  = (const float*)d_in[4];
    float* Y = (float*)d_out;

    int ntok    = in_sizes[0] / (64 * 3);   // B*N
    int ngroups = ntok / TOKBUF;            // 2048

    cudaFuncSetAttribute(affine_ws2,
                         cudaFuncAttributeMaxDynamicSharedMemorySize, SMEM_TOTAL);

    int blocks = 152;
    if (blocks > ngroups) blocks = ngroups;
    affine_ws2<<<blocks, THREADS, SMEM_TOTAL>>>(X, J, A, Bm, C, Y, ngroups);
}

// round 6
// speedup vs baseline: 2.1975x; 1.0724x over previous
#include <cuda_runtime.h>
#include <cuda_bf16.h>
#include <cstdint>

// Warp-specialized Affine_Linear (HMMA; tcgen05 unavailable on compute_103 target).
//  10 producer warps: frame build -> split-bf16 terms (double-buffered sA);
//                     Y epilogue = pure linear float4 copy (no index math).
//   6 consumer warps: m32n32 HMMA tiles, software-pipelined k-loop,
//                     acc scattered into Y-linear smem layout (offsets loop-invariant).

#define THREADS 512
#define NPROD   320
#define NCONS   192
#define TOKBUF  32
#define APITCH  392            // halves/row (784B = 49 chunks == 1 mod 8, ldsm conflict-free)
#define BPITCH  72             // halves/row (144B = 9 chunks == 1 mod 8)
#define SB_BYTES   (384*BPITCH*2)            // 55296
#define ABUF_BYTES (96*APITCH*2)             // 75264
#define SMEM_TOTAL (SB_BYTES + 2*ABUF_BYTES) // 205824

__device__ __forceinline__ uint32_t smem_u32(const void* p) {
    return (uint32_t)__cvta_generic_to_shared(p);
}
__device__ __forceinline__ void ldsm_x4(uint32_t* r, uint32_t addr) {
    asm volatile("ldmatrix.sync.aligned.m8n8.x4.shared.b16 {%0,%1,%2,%3}, [%4];"
                 : "=r"(r[0]), "=r"(r[1]), "=r"(r[2]), "=r"(r[3]) : "r"(addr));
}
__device__ __forceinline__ void ldsm_x4_t(uint32_t* r, uint32_t addr) {
    asm volatile("ldmatrix.sync.aligned.m8n8.x4.trans.shared.b16 {%0,%1,%2,%3}, [%4];"
                 : "=r"(r[0]), "=r"(r[1]), "=r"(r[2]), "=r"(r[3]) : "r"(addr));
}
__device__ __forceinline__ void mma16816(float* c, const uint32_t* a, uint32_t b0, uint32_t b1) {
    asm volatile("mma.sync.aligned.m16n8k16.row.col.f32.bf16.bf16.f32 "
                 "{%0,%1,%2,%3}, {%4,%5,%6,%7}, {%8,%9}, {%0,%1,%2,%3};"
                 : "+f"(c[0]), "+f"(c[1]), "+f"(c[2]), "+f"(c[3])
                 : "r"(a[0]), "r"(a[1]), "r"(a[2]), "r"(a[3]), "r"(b0), "r"(b1));
}

struct Frag {
    uint32_t ah0[4], ah1[4], al0[4], al1[4];
    uint32_t bh[2][4], bl[2][4];
};

__device__ __forceinline__ void load_frags(Frag& F, uint32_t aBase, uint32_t bBase, int ks) {
    uint32_t ao = (uint32_t)(ks * 32);
    ldsm_x4(F.ah0, aBase + ao);
    ldsm_x4(F.ah1, aBase + 16 * APITCH * 2 + ao);
    ldsm_x4(F.al0, aBase + 384 + ao);
    ldsm_x4(F.al1, aBase + 16 * APITCH * 2 + 384 + ao);
    uint32_t bo = (uint32_t)(ks * 16 * BPITCH * 2);
    ldsm_x4_t(F.bh[0], bBase + bo);
    ldsm_x4_t(F.bh[1], bBase + bo + 32);
    ldsm_x4_t(F.bl[0], bBase + bo + 192 * BPITCH * 2);
    ldsm_x4_t(F.bl[1], bBase + bo + 192 * BPITCH * 2 + 32);
}

__device__ __forceinline__ void do_mmas(float acc[2][4][4], const Frag& F) {
#pragma unroll
    for (int q = 0; q < 2; q++) {
#pragma unroll
        for (int j = 0; j < 2; j++) {
            uint32_t p0 = F.bh[q][2*j], p1 = F.bh[q][2*j+1];
            uint32_t l0 = F.bl[q][2*j], l1 = F.bl[q][2*j+1];
            float* c0 = acc[0][2*q+j];
            float* c1 = acc[1][2*q+j];
            mma16816(c0, F.ah0, p0, p1);   // Ah*Bh
            mma16816(c1, F.ah1, p0, p1);
            mma16816(c0, F.al0, p0, p1);   // Al*Bh
            mma16816(c1, F.al1, p0, p1);
            mma16816(c0, F.ah0, l0, l1);   // Ah*Bl
            mma16816(c1, F.ah1, l0, l1);
        }
    }
}

__device__ __forceinline__ void split2p(__nv_bfloat16* hi, __nv_bfloat16* lo, float v0, float v1) {
    __nv_bfloat16 h0 = __float2bfloat16(v0);
    __nv_bfloat16 h1 = __float2bfloat16(v1);
    *(__nv_bfloat162*)hi = __halves2bfloat162(h0, h1);
    *(__nv_bfloat162*)lo = __halves2bfloat162(__float2bfloat16(v0 - __bfloat162float(h0)),
                                              __float2bfloat16(v1 - __bfloat162float(h1)));
}

__device__ __forceinline__ void frame_terms(float a1x, float a2x, float a1y, float a2y,
                                            float a1z, float a2z,
                                            float x0, float x1, float x2, float t[3][3]) {
    float s1   = fmaf(a1x, a1x, fmaf(a1y, a1y, a1z * a1z));
    float inv1 = rsqrtf(fmaxf(s1, 1e-24f));
    float b1x = a1x * inv1, b1y = a1y * inv1, b1z = a1z * inv1;

    float d  = fmaf(b1x, a2x, fmaf(b1y, a2y, b1z * a2z));
    float ux = fmaf(-d, b1x, a2x);
    float uy = fmaf(-d, b1y, a2y);
    float uz = fmaf(-d, b1z, a2z);
    float s2   = fmaf(ux, ux, fmaf(uy, uy, uz * uz));
    float inv2 = rsqrtf(fmaxf(s2, 1e-24f));
    float b2x = ux * inv2, b2y = uy * inv2, b2z = uz * inv2;

    float b3x = fmaf(b1y, b2z, -b1z * b2y);
    float b3y = fmaf(b1z, b2x, -b1x * b2z);
    float b3z = fmaf(b1x, b2y, -b1y * b2x);

    float rt0 = fmaf(b1x, x0, fmaf(b1y, x1, b1z * x2));
    float rt1 = fmaf(b2x, x0, fmaf(b2y, x1, b2z * x2));
    float rt2 = fmaf(b3x, x0, fmaf(b3y, x1, b3z * x2));

    t[0][0] = fmaf(b1x, rt0,  b2x * rt1);
    t[0][1] = fmaf(b1y, rt0,  b2y * rt1);
    t[0][2] = fmaf(b1z, rt0,  b2z * rt1);
    t[1][0] = fmaf(b2x, rt0, -b1x * rt1);
    t[1][1] = fmaf(b2y, rt0, -b1y * rt1);
    t[1][2] = fmaf(b2z, rt0, -b1z * rt1);
    t[2][0] = b3x * rt2;
    t[2][1] = b3y * rt2;
    t[2][2] = b3z * rt2;
}

__global__ __launch_bounds__(THREADS, 1)
void affine_ws3(const float* __restrict__ X,
                const float* __restrict__ J,
                const float* __restrict__ A,
                const float* __restrict__ Bm,
                const float* __restrict__ C,
                float* __restrict__ Y,
                int ngroups)
{
    extern __shared__ char smem[];
    __nv_bfloat16* sB  = (__nv_bfloat16*)smem;               // [k(384)][f(64)] pitch BPITCH
    __nv_bfloat16* sA0 = (__nv_bfloat16*)(smem + SB_BYTES);  // two buffers [96][APITCH]

    const int tid = threadIdx.x;

    // ---- weights -> sB, split hi/lo, packed bf16x2 along f ----
    for (int q = tid; q < 2048; q += THREADS) {
        int e  = q & 63;
        int f0 = (q >> 6) << 1;
        float wa0 = A[f0 * 64 + e],  wa1 = A[(f0 + 1) * 64 + e];
        float wb0 = Bm[f0 * 64 + e], wb1 = Bm[(f0 + 1) * 64 + e];
        float wc0 = C[f0 * 64 + e],  wc1 = C[(f0 + 1) * 64 + e];
        int k = e * 3;
        split2p(&sB[(k+0)*BPITCH + f0], &sB[(192+k+0)*BPITCH + f0], wa0, wa1);
        split2p(&sB[(k+1)*BPITCH + f0], &sB[(192+k+1)*BPITCH + f0], wb0, wb1);
        split2p(&sB[(k+2)*BPITCH + f0], &sB[(192+k+2)*BPITCH + f0], wc0, wc1);
    }
    __syncthreads();

    int nit = 0;
    for (int g = blockIdx.x; g < ngroups; g += gridDim.x) nit++;

    if (tid < NPROD) {
        // ================= PRODUCERS (warps 0-9) =================
        int it = 0;
        for (int g = blockIdx.x; g < ngroups; g += gridDim.x, it++) {
            int buf = it & 1;
            __nv_bfloat16* sA = sA0 + buf * (ABUF_BYTES / 2);

            if (it >= 2) {
                int bid = 3 + buf;   // EMPTY: consumers wrote sOutY for group it-2
                asm volatile("bar.sync %0, %1;" :: "r"(bid), "n"(THREADS) : "memory");
                // pure linear copy: sOutY -> Y
                const float4* src = (const float4*)sA;
                float4* dst = (float4*)(Y +
                    ((long long)blockIdx.x + (long long)(it - 2) * gridDim.x) * (TOKBUF * 192));
                for (int q = tid; q < (TOKBUF * 192) / 4; q += NPROD)
                    dst[q] = src[q];
                asm volatile("bar.sync 6, %0;" :: "n"(NPROD) : "memory");
            }

            long long tokBase = (long long)g * TOKBUF;
            for (int p = tid; p < TOKBUF * 32; p += NPROD) {
                int tok = p >> 5;
                int e0  = (p & 31) << 1;
                long long base = (tokBase + tok) * 64 + e0;

                const float4* Jp = (const float4*)(J + base * 6);
                float4 j0 = Jp[0], j1 = Jp[1], j2 = Jp[2];
                const float2* Xp = (const float2*)(X + base * 3);
                float2 xa = Xp[0], xb = Xp[1], xc = Xp[2];

                float t0[3][3], t1[3][3];
                frame_terms(j0.x, j0.y, j0.z, j0.w, j1.x, j1.y, xa.x, xa.y, xb.x, t0);
                frame_terms(j1.z, j1.w, j2.x, j2.y, j2.z, j2.w, xb.y, xc.x, xc.y, t1);

                int k0 = 3 * e0;
#pragma unroll
                for (int i = 0; i < 3; i++) {
                    __nv_bfloat16* r = sA + (tok * 3 + i) * APITCH + k0;
                    split2p(r + 0, r + 192 + 0, t0[0][i], t0[1][i]);
                    split2p(r + 2, r + 192 + 2, t0[2][i], t1[0][i]);
                    split2p(r + 4, r + 192 + 4, t1[1][i], t1[2][i]);
                }
            }
            {
                int bid = 1 + buf;   // FULL
                asm volatile("bar.arrive %0, %1;" :: "r"(bid), "n"(THREADS) : "memory");
            }
        }
        // ---- drain: copy out the last <=2 sOutY buffers ----
#pragma unroll 1
        for (int k = 0; k < 2; k++) {
            int itd = nit + k;
            int src_it = itd - 2;
            if (src_it < 0 || src_it >= nit) continue;
            int buf = itd & 1;
            int bid = 3 + buf;
            asm volatile("bar.sync %0, %1;" :: "r"(bid), "n"(THREADS) : "memory");
            const float4* src = (const float4*)(sA0 + buf * (ABUF_BYTES / 2));
            float4* dst = (float4*)(Y +
                ((long long)blockIdx.x + (long long)src_it * gridDim.x) * (TOKBUF * 192));
            for (int q = tid; q < (TOKBUF * 192) / 4; q += NPROD)
                dst[q] = src[q];
        }
    } else {
        // ================= CONSUMERS (warps 10-15) =================
        const int cw   = (tid - NPROD) >> 5;   // 0..5
        const int lane = tid & 31;
        const int row0 = (cw >> 1) * 32;       // 3 m-tiles
        const int n0   = (cw & 1) * 32;        // 2 n-tiles
        const int gq   = lane >> 2;
        const int tq   = lane & 3;

        // loop-invariant Y-linear offsets for the 4 row variants (mt,half)
        int offY[4];
#pragma unroll
        for (int v = 0; v < 4; v++) {
            int r   = row0 + (v >> 1) * 16 + (v & 1) * 8 + gq;
            int tok = r / 3;
            offY[v] = tok * 192 + (r - 3 * tok);
        }

        const uint32_t bBase = smem_u32(sB + (lane & 15) * BPITCH + n0 + ((lane >> 4) << 3));

        int it = 0;
        for (int g = blockIdx.x; g < ngroups; g += gridDim.x, it++) {
            int buf = it & 1;
            {
                int bid = 1 + buf;   // FULL
                asm volatile("bar.sync %0, %1;" :: "r"(bid), "n"(THREADS) : "memory");
            }
            __nv_bfloat16* sA = sA0 + buf * (ABUF_BYTES / 2);
            float* sOutY = (float*)sA;

            uint32_t aBase = smem_u32(sA + (row0 + (lane & 15)) * APITCH + ((lane >> 4) << 3));

            float acc[2][4][4];
#pragma unroll
            for (int mt = 0; mt < 2; mt++)
#pragma unroll
                for (int q = 0; q < 4; q++)
#pragma unroll
                    for (int r = 0; r < 4; r++) acc[mt][q][r] = 0.f;

            // software-pipelined k-loop (12 steps, double-buffered fragments)
            Frag F[2];
            load_frags(F[0], aBase, bBase, 0);
#pragma unroll
            for (int ks = 0; ks < 12; ks++) {
                if (ks < 11) load_frags(F[(ks + 1) & 1], aBase, bBase, ks + 1);
                do_mmas(acc, F[ks & 1]);
            }

            // all consumers done reading sA before sOutY overwrite
            asm volatile("bar.sync 5, %0;" :: "n"(NCONS) : "memory");

            // scatter acc into Y-linear layout: sOutY[tok*192 + f*3 + i]
#pragma unroll
            for (int mt = 0; mt < 2; mt++) {
#pragma unroll
                for (int q = 0; q < 4; q++) {
                    int col3 = (n0 + q * 8 + tq * 2) * 3;
                    sOutY[offY[mt*2+0] + col3]     = acc[mt][q][0];
                    sOutY[offY[mt*2+0] + col3 + 3] = acc[mt][q][1];
                    sOutY[offY[mt*2+1] + col3]     = acc[mt][q][2];
                    sOutY[offY[mt*2+1] + col3 + 3] = acc[mt][q][3];
                }
            }
            {
                int bid = 3 + buf;   // EMPTY (sOutY ready for producer copy)
                asm volatile("bar.arrive %0, %1;" :: "r"(bid), "n"(THREADS) : "memory");
            }
        }
    }
}

extern "C" void kernel_launch(void* const* d_in, const int* in_sizes, int n_in,
                              void* d_out, int out_size)
{
    const float* X  = (const float*)d_in[0];
    const float* J  = (const float*)d_in[1];
    const float* A  = (const float*)d_in[2];
    const float* Bm = (const float*)d_in[3];
    const float* C  = (const float*)d_in[4];
    float* Y = (float*)d_out;

    int ntok    = in_sizes[0] / (64 * 3);   // B*N
    int ngroups = ntok / TOKBUF;            // 2048

    cudaFuncSetAttribute(affine_ws3,
                         cudaFuncAttributeMaxDynamicSharedMemorySize, SMEM_TOTAL);

    int blocks = 152;
    if (blocks > ngroups) blocks = ngroups;
    affine_ws3<<<blocks, THREADS, SMEM_TOTAL>>>(X, J, A, Bm, C, Y, ngroups);
}